// round 15
// baseline (speedup 1.0000x reference)
#include <cuda_runtime.h>
#include <cuda_bf16.h>
#include <cuda_fp16.h>
#include <math.h>
#include <stdint.h>

// ---------------- problem dims ----------------
#define N_ROWS 4096
#define C_DIM  1024
#define D_ROOT 2002
#define H0     256
#define H1     64
#define D0     8000
#define D1     40257

#define NT_ROOT 16
#define NT0     63
#define NT1     315
#define HCOMB   384

#define PAD_ROOT 46.f
#define PAD_T0   64.f
#define PAD_T1   63.f

#define LOG2E 1.4426950408889634f
#define LN2   0.6931471805599453f

#define TILE_BYTES  16384
#define STAGE3      32768
#define SMEM_DYN    (3 * STAGE3)

// launch A: proj (96) + root expsum (512)
#define NB_PROJ  96
#define NB_ROOT  (NT_ROOT * 32)              // 512
#define NB_A     (NB_PROJ + NB_ROOT)         // 608
// launch B: tail0 blocks + tail1 supertiles (4 row-tiles per block)
#define NB_T0    (NT0 * 32)                  // 2016
#define NB_T1S   (NT1 * 8)                   // 2520
#define NB_TAILS (NB_T0 + NB_T1S)            // 4536

// prep
#define NB_CONV  4096
#define NB_PREP  (NB_CONV + 6904)

// ---------------- scratch ----------------
__device__ __align__(16) __nv_bfloat16 g_xbf[N_ROWS * C_DIM];
__device__ __align__(16) __nv_bfloat16 g_hcomb[N_ROWS * HCOMB];
__device__ __align__(16) __nv_bfloat16 g_pt[HCOMB * C_DIM];
__device__ __align__(16) __nv_bfloat16 g_wtroot[NT_ROOT * 128 * C_DIM];   // * log2e
__device__ __align__(16) __nv_bfloat16 g_wt0[NT0 * 128 * H0];             // * log2e
__device__ __align__(16) __nv_bfloat16 g_wt1[(size_t)NT1 * 128 * H1];     // * log2e
__device__ float g_part_root[N_ROWS * NT_ROOT];
__device__ float g_part0[N_ROWS * NT0];
__device__ float g_part1[(size_t)N_ROWS * NT1];
__device__ float g_ce[3 * N_ROWS];

// ---------------- helpers ----------------
static __device__ __forceinline__ uint32_t smem_u32(const void* p) {
    uint32_t r;
    asm("{ .reg .u64 t; cvta.to.shared.u64 t, %1; cvt.u32.u64 %0, t; }" : "=r"(r) : "l"(p));
    return r;
}
static __device__ __forceinline__ void cp_async16(uint32_t dst, const void* src) {
    asm volatile("cp.async.cg.shared.global [%0], [%1], 16;" :: "r"(dst), "l"(src));
}
// two exps in one MUFU op: 2^a + 2^b accumulated into p (f16x2 path)
static __device__ __forceinline__ void ex2_pair_acc(float a, float b, float& p) {
    __half2 h = __floats2half2_rn(a, b);
    uint32_t hr = *reinterpret_cast<uint32_t*>(&h);
    uint32_t er;
    asm("ex2.approx.f16x2 %0, %1;" : "=r"(er) : "r"(hr));
    __half2 e = *reinterpret_cast<__half2*>(&er);
    float2 f = __half22float2(e);
    p += f.x + f.y;
}
#define CP_COMMIT()   asm volatile("cp.async.commit_group;")
#define CP_WAIT1()    asm volatile("cp.async.wait_group 1;")
#define CP_WAIT_N(n)  asm volatile("cp.async.wait_group %0;" :: "n"(n))

#define LDSM4(r0, r1, r2, r3, addr) \
    asm volatile("ldmatrix.sync.aligned.m8n8.x4.shared.b16 {%0,%1,%2,%3}, [%4];" \
        : "=r"(r0), "=r"(r1), "=r"(r2), "=r"(r3) : "r"(addr))

#define MMA16816(d, a, b0, b1) \
    asm volatile("mma.sync.aligned.m16n8k16.row.col.f32.bf16.bf16.f32 " \
        "{%0,%1,%2,%3}, {%4,%5,%6,%7}, {%8,%9}, {%0,%1,%2,%3};" \
        : "+f"((d)[0]), "+f"((d)[1]), "+f"((d)[2]), "+f"((d)[3]) \
        : "r"((a)[0]), "r"((a)[1]), "r"((a)[2]), "r"((a)[3]), "r"(b0), "r"(b1))

static __device__ __forceinline__ void zero_acc(float acc[4][4][4]) {
#pragma unroll
    for (int i = 0; i < 4; i++)
#pragma unroll
        for (int j = 0; j < 4; j++)
#pragma unroll
            for (int q = 0; q < 4; q++) acc[i][j][q] = 0.f;
}

// one 128x128x64 tile of MMAs out of SMEM (A at sA, B at sB)
static __device__ __forceinline__ void compute_tile(
    uint32_t sA, uint32_t sB, float acc[4][4][4],
    const uint32_t chunk[4], uint32_t aRowOff, uint32_t bRowOff)
{
#pragma unroll
    for (int ks = 0; ks < 4; ks++) {
        uint32_t a[4][4], b[2][4];
#pragma unroll
        for (int mt = 0; mt < 4; mt++)
            LDSM4(a[mt][0], a[mt][1], a[mt][2], a[mt][3],
                  sA + aRowOff + (uint32_t)(mt << 11) + chunk[ks]);
#pragma unroll
        for (int np = 0; np < 2; np++)
            LDSM4(b[np][0], b[np][1], b[np][2], b[np][3],
                  sB + bRowOff + (uint32_t)(np << 11) + chunk[ks]);
#pragma unroll
        for (int mt = 0; mt < 4; mt++) {
#pragma unroll
            for (int np = 0; np < 2; np++) {
                MMA16816(acc[mt][2 * np],     a[mt], b[np][0], b[np][2]);
                MMA16816(acc[mt][2 * np + 1], a[mt], b[np][1], b[np][3]);
            }
        }
    }
}

// ---------------- 3-stage mainloop: 128x128 tile, BK=64 ----------------
static __device__ __forceinline__ void gemm_mainloop(
    const __nv_bfloat16* __restrict__ A, int lda,
    const __nv_bfloat16* __restrict__ B, int K,
    int row0, int col0, uint32_t sBase, float acc[4][4][4])
{
    const int tid = threadIdx.x;
    const int lane = tid & 31, wid = tid >> 5;
    const int warp_m = wid & 1, warp_n = wid >> 1;

    zero_acc(acc);

    const int r0 = tid >> 3;
    const __nv_bfloat16* gA = A + (size_t)(row0 + r0) * lda + ((tid & 7) << 3);
    const __nv_bfloat16* gB = B + (size_t)(col0 + r0) * K + ((tid & 7) << 3);
    const size_t strA = (size_t)lda << 5, strB = (size_t)K << 5;
    const uint32_t soff = ((uint32_t)r0 << 7) + (uint32_t)(((tid & 7) ^ (r0 & 7)) << 4);

    auto load_stage = [&](int stage, int kt) {
        uint32_t sA = sBase + (uint32_t)stage * STAGE3 + soff;
        const __nv_bfloat16* pA = gA + (kt << 6);
        const __nv_bfloat16* pB = gB + (kt << 6);
#pragma unroll
        for (int i = 0; i < 4; i++) {
            cp_async16(sA, pA);
            cp_async16(sA + TILE_BYTES, pB);
            sA += 4096; pA += strA; pB += strB;
        }
    };

    const int lane7 = lane & 7;
    const int b3 = (lane >> 3) & 1, b4 = (lane >> 4) & 1;
    const uint32_t aRowOff = (uint32_t)((warp_m * 64 + lane7 + 8 * b3) << 7);
    const uint32_t bRowOff = (uint32_t)((warp_n * 32 + lane7 + 8 * b3) << 7);
    uint32_t chunk[4];
#pragma unroll
    for (int ks = 0; ks < 4; ks++)
        chunk[ks] = (uint32_t)((((ks << 1) + b4) ^ lane7) << 4);

    const int nk = K >> 6;
    load_stage(0, 0);
    CP_COMMIT();
    if (nk > 1) load_stage(1, 1);
    CP_COMMIT();

    int stage = 0;
    for (int kt = 0; kt < nk; kt++) {
        CP_WAIT1();
        __syncthreads();
        const uint32_t sA = sBase + (uint32_t)stage * STAGE3;
        compute_tile(sA, sA + TILE_BYTES, acc, chunk, aRowOff, bRowOff);
        if (kt + 2 < nk) {
            int ps = stage + 2; if (ps >= 3) ps -= 3;
            load_stage(ps, kt + 2);
        }
        CP_COMMIT();
        if (++stage == 3) stage = 0;
    }
    __syncthreads();
}

// ---------------- shared exp-sum epilogue (f16x2 ex2) ----------------
static __device__ __forceinline__ void expsum_epilogue(
    float acc[4][4][4], float* part, int ntiles, int row0, int ct, char* redmem)
{
    const int tid = threadIdx.x;
    const int lane = tid & 31, wid = tid >> 5;
    const int warp_m = wid & 1, warp_n = wid >> 1;
    float* red = reinterpret_cast<float*>(redmem);
#pragma unroll
    for (int mt = 0; mt < 4; mt++) {
#pragma unroll
        for (int h = 0; h < 2; h++) {
            float p = 0.f;
#pragma unroll
            for (int nt = 0; nt < 4; nt++)
                ex2_pair_acc(acc[mt][nt][2 * h], acc[mt][nt][2 * h + 1], p);
            p += __shfl_xor_sync(0xffffffffu, p, 1);
            p += __shfl_xor_sync(0xffffffffu, p, 2);
            if ((lane & 3) == 0) {
                int r = warp_m * 64 + mt * 16 + (lane >> 2) + 8 * h;
                red[r * 4 + warp_n] = p;
            }
        }
    }
    __syncthreads();
    if (tid < 128) {
        float s = red[tid * 4] + red[tid * 4 + 1] + red[tid * 4 + 2] + red[tid * 4 + 3];
        part[(size_t)(row0 + tid) * ntiles + ct] = s;
    }
}

// ---------------- prep: convert + all transposes in ONE launch ----------------
__global__ __launch_bounds__(256)
void prep_all(const float* __restrict__ logits,
              const float* __restrict__ head_kernel,
              const float* __restrict__ proj0, const float* __restrict__ proj1,
              const float* __restrict__ scale0, const float* __restrict__ scale1)
{
    int b = blockIdx.x;
    int tid = threadIdx.x;
    if (b < NB_CONV) {
        int i = b * 256 + tid;
        float4 v = reinterpret_cast<const float4*>(logits)[i];
        reinterpret_cast<__nv_bfloat162*>(g_xbf)[2 * i]     = __floats2bfloat162_rn(v.x, v.y);
        reinterpret_cast<__nv_bfloat162*>(g_xbf)[2 * i + 1] = __floats2bfloat162_rn(v.z, v.w);
        return;
    }
    b -= NB_CONV;
    const float* W; __nv_bfloat16* Wt; int K, D, nd; float sc = LOG2E;
    if (b < 2048)      { W = head_kernel; Wt = g_wtroot;            K = 1024; D = D_ROOT; nd = 64; }
    else if (b < 2304) { b -= 2048; W = proj0;  Wt = g_pt;              K = 1024; D = H0; nd = 8; sc = 1.f; }
    else if (b < 2368) { b -= 2304; W = proj1;  Wt = g_pt + 256 * 1024; K = 1024; D = H1; nd = 2; sc = 1.f; }
    else if (b < 4384) { b -= 2368; W = scale0; Wt = g_wt0;             K = 256;  D = D0; nd = 252; }
    else               { b -= 4384; W = scale1; Wt = g_wt1;             K = 64;   D = D1; nd = 1260; }
    int d0 = (b % nd) * 32, k0 = (b / nd) * 32;

    __shared__ float sh[32][33];
    int tx = tid & 31, ty = tid >> 5;
#pragma unroll
    for (int i = 0; i < 4; i++) {
        int k = k0 + ty + i * 8;
        int d = d0 + tx;
        sh[ty + i * 8][tx] = (d < D) ? W[(size_t)k * D + d] * sc : 0.f;
    }
    __syncthreads();
#pragma unroll
    for (int i = 0; i < 4; i++) {
        int drow = d0 + ty + i * 8;
        Wt[(size_t)drow * K + k0 + tx] = __float2bfloat16(sh[tx][ty + i * 8]);
    }
}

// ---------------- launch A: proj GEMM (96) + root expsum (512) -------------
__global__ void __launch_bounds__(256)
gemm_root_proj(const __nv_bfloat16* __restrict__ xbf)
{
    extern __shared__ __align__(1024) char smem[];
    int bid = blockIdx.x;
    float acc[4][4][4];

    if (bid < NB_PROJ) {
        const int ct = bid % 3, rt = bid / 3;
        const int row0 = rt << 7, col0 = ct << 7;
        gemm_mainloop(xbf, C_DIM, g_pt, C_DIM, row0, col0, smem_u32(smem), acc);
        const int lane = threadIdx.x & 31, wid = threadIdx.x >> 5;
        const int warp_m = wid & 1, warp_n = wid >> 1;
#pragma unroll
        for (int mt = 0; mt < 4; mt++) {
#pragma unroll
            for (int h = 0; h < 2; h++) {
                int row = row0 + warp_m * 64 + mt * 16 + (lane >> 2) + 8 * h;
#pragma unroll
                for (int nt = 0; nt < 4; nt++) {
                    int gc = col0 + warp_n * 32 + nt * 8 + 2 * (lane & 3);
                    __nv_bfloat162 v = __floats2bfloat162_rn(acc[mt][nt][2 * h],
                                                             acc[mt][nt][2 * h + 1]);
                    *reinterpret_cast<__nv_bfloat162*>(g_hcomb + (size_t)row * HCOMB + gc) = v;
                }
            }
        }
    } else {
        const int tile = bid - NB_PROJ;
        const int ct = tile % NT_ROOT, rt = tile / NT_ROOT;
        const int row0 = rt << 7, col0 = ct << 7;
        gemm_mainloop(xbf, C_DIM, g_wtroot, C_DIM, row0, col0, smem_u32(smem), acc);
        expsum_epilogue(acc, g_part_root, NT_ROOT, row0, ct, smem);
    }
}

// ---------------- launch B: tail0 + tail1 4-row supertiles ------------------
__global__ void __launch_bounds__(256)
gemm_tails()
{
    extern __shared__ __align__(1024) char smem[];
    const uint32_t sBase = smem_u32(smem);
    const int tid = threadIdx.x;
    const int lane = tid & 31, wid = tid >> 5;
    const int warp_m = wid & 1, warp_n = wid >> 1;
    const int lane7 = lane & 7;
    const int b3 = (lane >> 3) & 1, b4 = (lane >> 4) & 1;
    const uint32_t aRowOff = (uint32_t)((warp_m * 64 + lane7 + 8 * b3) << 7);
    const uint32_t bRowOff = (uint32_t)((warp_n * 32 + lane7 + 8 * b3) << 7);
    uint32_t chunk[4];
#pragma unroll
    for (int ks = 0; ks < 4; ks++)
        chunk[ks] = (uint32_t)((((ks << 1) + b4) ^ lane7) << 4);

    const long long i = blockIdx.x;
    const int lo = (int)((i * NB_T1S) / NB_TAILS);
    const int hi = (int)(((i + 1) * NB_T1S) / NB_TAILS);
    float acc[4][4][4];

    if (hi > lo) {
        // ---- tail1 supertile: one B tile shared by FOUR row-tiles ----
        const int ct = lo % NT1, srt = lo / NT1;
        const int col0 = ct << 7;
        const int row0 = srt << 9;
        const int r0 = tid >> 3;
        const __nv_bfloat16* gB = g_wt1 + (size_t)(col0 + r0) * H1 + ((tid & 7) << 3);
        const __nv_bfloat16* gA = g_hcomb + 256 + (size_t)(row0 + r0) * HCOMB + ((tid & 7) << 3);
        const size_t strA = (size_t)HCOMB << 5, strB = (size_t)H1 << 5;
        const uint32_t soff = ((uint32_t)r0 << 7) + (uint32_t)(((tid & 7) ^ (r0 & 7)) << 4);

        {   // group0: B + A0
            uint32_t s = sBase + soff;
            const __nv_bfloat16 *pB = gB, *pA = gA;
#pragma unroll
            for (int q = 0; q < 4; q++) {
                cp_async16(s, pB);
                cp_async16(s + TILE_BYTES, pA);
                s += 4096; pB += strB; pA += strA;
            }
        }
        CP_COMMIT();
#pragma unroll
        for (int sub = 1; sub < 4; sub++) {
            uint32_t s = sBase + (uint32_t)(1 + sub) * TILE_BYTES + soff;
            const __nv_bfloat16* pA = gA + (size_t)(128 * sub) * HCOMB;
#pragma unroll
            for (int q = 0; q < 4; q++) {
                cp_async16(s, pA);
                s += 4096; pA += strA;
            }
            CP_COMMIT();
        }

        char* redmem = smem + 5 * TILE_BYTES;

#define DO_SUB(S, WAITN)                                                     \
        CP_WAIT_N(WAITN);                                                    \
        __syncthreads();                                                     \
        zero_acc(acc);                                                       \
        compute_tile(sBase + (uint32_t)(1 + (S)) * TILE_BYTES, sBase, acc,   \
                     chunk, aRowOff, bRowOff);                               \
        expsum_epilogue(acc, g_part1, NT1, row0 + 128 * (S), ct, redmem);    \
        __syncthreads();

        DO_SUB(0, 3)
        DO_SUB(1, 2)
        DO_SUB(2, 1)
        DO_SUB(3, 0)
#undef DO_SUB
    } else {
        // ---- tail0 tile ----
        const int tile = (int)i - lo;
        const int ct = tile % NT0, rt = tile / NT0;
        const int row0 = rt << 7, col0 = ct << 7;
        gemm_mainloop(g_hcomb, HCOMB, g_wt0, H0, row0, col0, sBase, acc);
        expsum_epilogue(acc, g_part0, NT0, row0, ct, smem);
    }
}

// ---------------- per-row CE: 2 rows per 256-thread block ----------------
__global__ __launch_bounds__(256)
void row_ce(const int* __restrict__ targets)
{
    const int tid = threadIdx.x;
    const int g   = tid >> 7;            // row half: 0 or 1
    const int t1d = tid & 127;           // lane within the row group
    const int n   = blockIdx.x * 2 + g;

    int t   = targets[n];
    int rt  = (t < 2000) ? t : ((t < 10000) ? 2000 : 2001);
    int t0  = min(max(t - 2000, 0), D0 - 1);
    int t1  = min(max(t - 10000, 0), D1 - 1);

    float sr = 0.f, s0 = 0.f, s1 = 0.f;
    const __nv_bfloat16* xr = g_xbf + (size_t)n * C_DIM;
    const __nv_bfloat16* wr = g_wtroot + (size_t)rt * C_DIM;
#pragma unroll
    for (int i = 0; i < 4; i++) {
        int k = 2 * t1d + i * 256;
        __nv_bfloat162 x2 = *reinterpret_cast<const __nv_bfloat162*>(xr + k);
        __nv_bfloat162 w2 = *reinterpret_cast<const __nv_bfloat162*>(wr + k);
        sr += __bfloat162float(x2.x) * __bfloat162float(w2.x)
            + __bfloat162float(x2.y) * __bfloat162float(w2.y);
    }
    const __nv_bfloat16* h = g_hcomb + (size_t)n * HCOMB;
    const __nv_bfloat16* w0 = g_wt0 + (size_t)t0 * H0;
#pragma unroll
    for (int i = 0; i < 2; i++) {
        int k = t1d + i * 128;
        s0 += __bfloat162float(h[k]) * __bfloat162float(w0[k]);
    }
    if (t1d < H1)
        s1 = __bfloat162float(h[256 + t1d]) * __bfloat162float(g_wt1[(size_t)t1 * H1 + t1d]);

    float pr = 0.f, p0 = 0.f, p1 = 0.f;
    if (t1d < NT_ROOT) pr = g_part_root[(size_t)n * NT_ROOT + t1d];
    for (int k = t1d; k < NT0; k += 128) p0 += g_part0[(size_t)n * NT0 + k];
    for (int k = t1d; k < NT1; k += 128) p1 += g_part1[(size_t)n * NT1 + k];

    __shared__ float sh[6][256];
    const int base = g * 128;
    sh[0][base + t1d] = sr; sh[1][base + t1d] = s0; sh[2][base + t1d] = s1;
    sh[3][base + t1d] = pr; sh[4][base + t1d] = p0; sh[5][base + t1d] = p1;
    __syncthreads();
    for (int off = 64; off > 0; off >>= 1) {
        if (t1d < off) {
#pragma unroll
            for (int q = 0; q < 6; q++)
                sh[q][base + t1d] += sh[q][base + t1d + off];
        }
        __syncthreads();
    }
    if (t1d == 0) {
        g_ce[n]              = logf(sh[3][base] - PAD_ROOT) - sh[0][base] * LN2;
        g_ce[N_ROWS + n]     = logf(sh[4][base] - PAD_T0)   - sh[1][base] * LN2;
        g_ce[2 * N_ROWS + n] = logf(sh[5][base] - PAD_T1)   - sh[2][base] * LN2;
    }
}

// ---------------- final scalar: shuffle-based, 1 sync ----------------
__global__ __launch_bounds__(512)
void final_kernel(const int* __restrict__ targets, float* __restrict__ out)
{
    const int tid = threadIdx.x;
    const int lane = tid & 31, wid = tid >> 5;   // 16 warps
    float v0 = 0.f, v1 = 0.f, v2 = 0.f, v3 = 0.f, v4 = 0.f;
#pragma unroll
    for (int i = 0; i < 8; i++) {
        int n = tid + i * 512;
        v0 += g_ce[n];
        int t = targets[n];
        if (t >= 2000 && t < 10000) { v1 += g_ce[N_ROWS + n];     v2 += 1.f; }
        if (t >= 10000)             { v3 += g_ce[2 * N_ROWS + n]; v4 += 1.f; }
    }
#pragma unroll
    for (int off = 16; off > 0; off >>= 1) {
        v0 += __shfl_xor_sync(0xffffffffu, v0, off);
        v1 += __shfl_xor_sync(0xffffffffu, v1, off);
        v2 += __shfl_xor_sync(0xffffffffu, v2, off);
        v3 += __shfl_xor_sync(0xffffffffu, v3, off);
        v4 += __shfl_xor_sync(0xffffffffu, v4, off);
    }
    __shared__ float sh[5][16];
    if (lane == 0) {
        sh[0][wid] = v0; sh[1][wid] = v1; sh[2][wid] = v2;
        sh[3][wid] = v3; sh[4][wid] = v4;
    }
    __syncthreads();
    if (tid < 32) {
        float w0 = (lane < 16) ? sh[0][lane] : 0.f;
        float w1 = (lane < 16) ? sh[1][lane] : 0.f;
        float w2 = (lane < 16) ? sh[2][lane] : 0.f;
        float w3 = (lane < 16) ? sh[3][lane] : 0.f;
        float w4 = (lane < 16) ? sh[4][lane] : 0.f;
#pragma unroll
        for (int off = 8; off > 0; off >>= 1) {
            w0 += __shfl_xor_sync(0xffffffffu, w0, off);
            w1 += __shfl_xor_sync(0xffffffffu, w1, off);
            w2 += __shfl_xor_sync(0xffffffffu, w2, off);
            w3 += __shfl_xor_sync(0xffffffffu, w3, off);
            w4 += __shfl_xor_sync(0xffffffffu, w4, off);
        }
        if (lane == 0) {
            float root_loss = w0 / (float)N_ROWS;
            float l0 = w1 / fmaxf(w2, 1.f);
            float l1 = w3 / fmaxf(w4, 1.f);
            out[0] = (root_loss + l0 + l1) / 3.f;
        }
    }
}

// ---------------- host launch ----------------
extern "C" void kernel_launch(void* const* d_in, const int* in_sizes, int n_in,
                              void* d_out, int out_size)
{
    const float* logits      = (const float*)d_in[0];
    const int*   targets     = (const int*)  d_in[1];
    const float* head_kernel = (const float*)d_in[2];
    const float* proj0       = (const float*)d_in[3];
    const float* scale0      = (const float*)d_in[4];
    const float* proj1       = (const float*)d_in[5];
    const float* scale1      = (const float*)d_in[6];
    float* out = (float*)d_out;

    __nv_bfloat16* xbf;
    cudaGetSymbolAddress((void**)&xbf, g_xbf);

    cudaFuncSetAttribute(gemm_root_proj, cudaFuncAttributeMaxDynamicSharedMemorySize, SMEM_DYN);
    cudaFuncSetAttribute(gemm_tails,     cudaFuncAttributeMaxDynamicSharedMemorySize, SMEM_DYN);

    // 1. prep: convert + transposes
    prep_all<<<NB_PREP, 256>>>(logits, head_kernel, proj0, proj1, scale0, scale1);

    // 2. launch A: hcomb projection + root expsum
    gemm_root_proj<<<NB_A, 256, SMEM_DYN>>>(xbf);

    // 3. launch B: tail0 + tail1 4-row supertiles
    gemm_tails<<<NB_TAILS, 256, SMEM_DYN>>>();

    // 4. per-row CE (2 rows/block), final scalar (shuffle reduction)
    row_ce<<<N_ROWS / 2, 256>>>(targets);
    final_kernel<<<1, 512>>>(targets, out);
}

// round 16
// speedup vs baseline: 1.0070x; 1.0070x over previous
#include <cuda_runtime.h>
#include <cuda_bf16.h>
#include <cuda_fp16.h>
#include <math.h>
#include <stdint.h>

// ---------------- problem dims ----------------
#define N_ROWS 4096
#define C_DIM  1024
#define D_ROOT 2002
#define H0     256
#define H1     64
#define D0     8000
#define D1     40257

#define NT_ROOT 16
#define NT0     63
#define NT1     315
#define HCOMB   384

#define PAD_ROOT 46.f
#define PAD_T0   64.f
#define PAD_T1   63.f

#define LOG2E 1.4426950408889634f
#define LN2   0.6931471805599453f

#define TILE_BYTES  16384
#define STAGE3      32768
#define SMEM_DYN    (3 * STAGE3)

// launch A: proj (96) + root expsum (512)
#define NB_PROJ  96
#define NB_ROOT  (NT_ROOT * 32)              // 512
#define NB_A     (NB_PROJ + NB_ROOT)         // 608
// launch B: tail0 blocks + tail1 supertiles (4 row-tiles per block)
#define NB_T0    (NT0 * 32)                  // 2016
#define NB_T1S   (NT1 * 8)                   // 2520
#define NB_TAILS (NB_T0 + NB_T1S)            // 4536

// prep
#define NB_CONV  4096
#define NB_PREP  (NB_CONV + 6904)

// ---------------- scratch ----------------
__device__ __align__(16) __nv_bfloat16 g_xbf[N_ROWS * C_DIM];
__device__ __align__(16) __nv_bfloat16 g_hcomb[N_ROWS * HCOMB];
__device__ __align__(16) __nv_bfloat16 g_pt[HCOMB * C_DIM];
__device__ __align__(16) __nv_bfloat16 g_wtroot[NT_ROOT * 128 * C_DIM];   // * log2e
__device__ __align__(16) __nv_bfloat16 g_wt0[NT0 * 128 * H0];             // * log2e
__device__ __align__(16) __nv_bfloat16 g_wt1[(size_t)NT1 * 128 * H1];     // * log2e
__device__ float g_part_root[N_ROWS * NT_ROOT];
__device__ float g_part0[N_ROWS * NT0];
__device__ float g_part1[(size_t)N_ROWS * NT1];
__device__ float g_ce[3 * N_ROWS];

// ---------------- helpers ----------------
static __device__ __forceinline__ uint32_t smem_u32(const void* p) {
    uint32_t r;
    asm("{ .reg .u64 t; cvta.to.shared.u64 t, %1; cvt.u32.u64 %0, t; }" : "=r"(r) : "l"(p));
    return r;
}
static __device__ __forceinline__ void cp_async16(uint32_t dst, const void* src) {
    asm volatile("cp.async.cg.shared.global [%0], [%1], 16;" :: "r"(dst), "l"(src));
}
// two exps in one MUFU op: 2^a + 2^b accumulated into p (f16x2 path)
static __device__ __forceinline__ void ex2_pair_acc(float a, float b, float& p) {
    __half2 h = __floats2half2_rn(a, b);
    uint32_t hr = *reinterpret_cast<uint32_t*>(&h);
    uint32_t er;
    asm("ex2.approx.f16x2 %0, %1;" : "=r"(er) : "r"(hr));
    __half2 e = *reinterpret_cast<__half2*>(&er);
    float2 f = __half22float2(e);
    p += f.x + f.y;
}
#define CP_COMMIT()   asm volatile("cp.async.commit_group;")
#define CP_WAIT1()    asm volatile("cp.async.wait_group 1;")
#define CP_WAIT_N(n)  asm volatile("cp.async.wait_group %0;" :: "n"(n))

#define LDSM4(r0, r1, r2, r3, addr) \
    asm volatile("ldmatrix.sync.aligned.m8n8.x4.shared.b16 {%0,%1,%2,%3}, [%4];" \
        : "=r"(r0), "=r"(r1), "=r"(r2), "=r"(r3) : "r"(addr))

#define MMA16816(d, a, b0, b1) \
    asm volatile("mma.sync.aligned.m16n8k16.row.col.f32.bf16.bf16.f32 " \
        "{%0,%1,%2,%3}, {%4,%5,%6,%7}, {%8,%9}, {%0,%1,%2,%3};" \
        : "+f"((d)[0]), "+f"((d)[1]), "+f"((d)[2]), "+f"((d)[3]) \
        : "r"((a)[0]), "r"((a)[1]), "r"((a)[2]), "r"((a)[3]), "r"(b0), "r"(b1))

static __device__ __forceinline__ void zero_acc(float acc[4][4][4]) {
#pragma unroll
    for (int i = 0; i < 4; i++)
#pragma unroll
        for (int j = 0; j < 4; j++)
#pragma unroll
            for (int q = 0; q < 4; q++) acc[i][j][q] = 0.f;
}

// one 128x128x64 tile of MMAs out of SMEM (A at sA, B at sB)
static __device__ __forceinline__ void compute_tile(
    uint32_t sA, uint32_t sB, float acc[4][4][4],
    const uint32_t chunk[4], uint32_t aRowOff, uint32_t bRowOff)
{
#pragma unroll
    for (int ks = 0; ks < 4; ks++) {
        uint32_t a[4][4], b[2][4];
#pragma unroll
        for (int mt = 0; mt < 4; mt++)
            LDSM4(a[mt][0], a[mt][1], a[mt][2], a[mt][3],
                  sA + aRowOff + (uint32_t)(mt << 11) + chunk[ks]);
#pragma unroll
        for (int np = 0; np < 2; np++)
            LDSM4(b[np][0], b[np][1], b[np][2], b[np][3],
                  sB + bRowOff + (uint32_t)(np << 11) + chunk[ks]);
#pragma unroll
        for (int mt = 0; mt < 4; mt++) {
#pragma unroll
            for (int np = 0; np < 2; np++) {
                MMA16816(acc[mt][2 * np],     a[mt], b[np][0], b[np][2]);
                MMA16816(acc[mt][2 * np + 1], a[mt], b[np][1], b[np][3]);
            }
        }
    }
}

// ---------------- 3-stage mainloop: 128x128 tile, BK=64 ----------------
static __device__ __forceinline__ void gemm_mainloop(
    const __nv_bfloat16* __restrict__ A, int lda,
    const __nv_bfloat16* __restrict__ B, int K,
    int row0, int col0, uint32_t sBase, float acc[4][4][4])
{
    const int tid = threadIdx.x;
    const int lane = tid & 31, wid = tid >> 5;
    const int warp_m = wid & 1, warp_n = wid >> 1;

    zero_acc(acc);

    const int r0 = tid >> 3;
    const __nv_bfloat16* gA = A + (size_t)(row0 + r0) * lda + ((tid & 7) << 3);
    const __nv_bfloat16* gB = B + (size_t)(col0 + r0) * K + ((tid & 7) << 3);
    const size_t strA = (size_t)lda << 5, strB = (size_t)K << 5;
    const uint32_t soff = ((uint32_t)r0 << 7) + (uint32_t)(((tid & 7) ^ (r0 & 7)) << 4);

    auto load_stage = [&](int stage, int kt) {
        uint32_t sA = sBase + (uint32_t)stage * STAGE3 + soff;
        const __nv_bfloat16* pA = gA + (kt << 6);
        const __nv_bfloat16* pB = gB + (kt << 6);
#pragma unroll
        for (int i = 0; i < 4; i++) {
            cp_async16(sA, pA);
            cp_async16(sA + TILE_BYTES, pB);
            sA += 4096; pA += strA; pB += strB;
        }
    };

    const int lane7 = lane & 7;
    const int b3 = (lane >> 3) & 1, b4 = (lane >> 4) & 1;
    const uint32_t aRowOff = (uint32_t)((warp_m * 64 + lane7 + 8 * b3) << 7);
    const uint32_t bRowOff = (uint32_t)((warp_n * 32 + lane7 + 8 * b3) << 7);
    uint32_t chunk[4];
#pragma unroll
    for (int ks = 0; ks < 4; ks++)
        chunk[ks] = (uint32_t)((((ks << 1) + b4) ^ lane7) << 4);

    const int nk = K >> 6;
    load_stage(0, 0);
    CP_COMMIT();
    if (nk > 1) load_stage(1, 1);
    CP_COMMIT();

    int stage = 0;
    for (int kt = 0; kt < nk; kt++) {
        CP_WAIT1();
        __syncthreads();
        const uint32_t sA = sBase + (uint32_t)stage * STAGE3;
        compute_tile(sA, sA + TILE_BYTES, acc, chunk, aRowOff, bRowOff);
        if (kt + 2 < nk) {
            int ps = stage + 2; if (ps >= 3) ps -= 3;
            load_stage(ps, kt + 2);
        }
        CP_COMMIT();
        if (++stage == 3) stage = 0;
    }
    __syncthreads();
}

// ---------------- shared exp-sum epilogue (f16x2 ex2) ----------------
static __device__ __forceinline__ void expsum_epilogue(
    float acc[4][4][4], float* part, int ntiles, int row0, int ct, char* redmem)
{
    const int tid = threadIdx.x;
    const int lane = tid & 31, wid = tid >> 5;
    const int warp_m = wid & 1, warp_n = wid >> 1;
    float* red = reinterpret_cast<float*>(redmem);
#pragma unroll
    for (int mt = 0; mt < 4; mt++) {
#pragma unroll
        for (int h = 0; h < 2; h++) {
            float p = 0.f;
#pragma unroll
            for (int nt = 0; nt < 4; nt++)
                ex2_pair_acc(acc[mt][nt][2 * h], acc[mt][nt][2 * h + 1], p);
            p += __shfl_xor_sync(0xffffffffu, p, 1);
            p += __shfl_xor_sync(0xffffffffu, p, 2);
            if ((lane & 3) == 0) {
                int r = warp_m * 64 + mt * 16 + (lane >> 2) + 8 * h;
                red[r * 4 + warp_n] = p;
            }
        }
    }
    __syncthreads();
    if (tid < 128) {
        float s = red[tid * 4] + red[tid * 4 + 1] + red[tid * 4 + 2] + red[tid * 4 + 3];
        part[(size_t)(row0 + tid) * ntiles + ct] = s;
    }
}

// ---------------- prep: convert + all transposes in ONE launch ----------------
__global__ __launch_bounds__(256)
void prep_all(const float* __restrict__ logits,
              const float* __restrict__ head_kernel,
              const float* __restrict__ proj0, const float* __restrict__ proj1,
              const float* __restrict__ scale0, const float* __restrict__ scale1)
{
    int b = blockIdx.x;
    int tid = threadIdx.x;
    if (b < NB_CONV) {
        int i = b * 256 + tid;
        float4 v = reinterpret_cast<const float4*>(logits)[i];
        reinterpret_cast<__nv_bfloat162*>(g_xbf)[2 * i]     = __floats2bfloat162_rn(v.x, v.y);
        reinterpret_cast<__nv_bfloat162*>(g_xbf)[2 * i + 1] = __floats2bfloat162_rn(v.z, v.w);
        return;
    }
    b -= NB_CONV;
    const float* W; __nv_bfloat16* Wt; int K, D, nd; float sc = LOG2E;
    if (b < 2048)      { W = head_kernel; Wt = g_wtroot;            K = 1024; D = D_ROOT; nd = 64; }
    else if (b < 2304) { b -= 2048; W = proj0;  Wt = g_pt;              K = 1024; D = H0; nd = 8; sc = 1.f; }
    else if (b < 2368) { b -= 2304; W = proj1;  Wt = g_pt + 256 * 1024; K = 1024; D = H1; nd = 2; sc = 1.f; }
    else if (b < 4384) { b -= 2368; W = scale0; Wt = g_wt0;             K = 256;  D = D0; nd = 252; }
    else               { b -= 4384; W = scale1; Wt = g_wt1;             K = 64;   D = D1; nd = 1260; }
    int d0 = (b % nd) * 32, k0 = (b / nd) * 32;

    __shared__ float sh[32][33];
    int tx = tid & 31, ty = tid >> 5;
#pragma unroll
    for (int i = 0; i < 4; i++) {
        int k = k0 + ty + i * 8;
        int d = d0 + tx;
        sh[ty + i * 8][tx] = (d < D) ? W[(size_t)k * D + d] * sc : 0.f;
    }
    __syncthreads();
#pragma unroll
    for (int i = 0; i < 4; i++) {
        int drow = d0 + ty + i * 8;
        Wt[(size_t)drow * K + k0 + tx] = __float2bfloat16(sh[tx][ty + i * 8]);
    }
}

// ---------------- launch A: proj GEMM (96) + root expsum (512) -------------
__global__ void __launch_bounds__(256)
gemm_root_proj(const __nv_bfloat16* __restrict__ xbf)
{
    extern __shared__ __align__(1024) char smem[];
    int bid = blockIdx.x;
    float acc[4][4][4];

    if (bid < NB_PROJ) {
        const int ct = bid % 3, rt = bid / 3;
        const int row0 = rt << 7, col0 = ct << 7;
        gemm_mainloop(xbf, C_DIM, g_pt, C_DIM, row0, col0, smem_u32(smem), acc);
        const int lane = threadIdx.x & 31, wid = threadIdx.x >> 5;
        const int warp_m = wid & 1, warp_n = wid >> 1;
#pragma unroll
        for (int mt = 0; mt < 4; mt++) {
#pragma unroll
            for (int h = 0; h < 2; h++) {
                int row = row0 + warp_m * 64 + mt * 16 + (lane >> 2) + 8 * h;
#pragma unroll
                for (int nt = 0; nt < 4; nt++) {
                    int gc = col0 + warp_n * 32 + nt * 8 + 2 * (lane & 3);
                    __nv_bfloat162 v = __floats2bfloat162_rn(acc[mt][nt][2 * h],
                                                             acc[mt][nt][2 * h + 1]);
                    *reinterpret_cast<__nv_bfloat162*>(g_hcomb + (size_t)row * HCOMB + gc) = v;
                }
            }
        }
    } else {
        const int tile = bid - NB_PROJ;
        const int ct = tile % NT_ROOT, rt = tile / NT_ROOT;
        const int row0 = rt << 7, col0 = ct << 7;
        gemm_mainloop(xbf, C_DIM, g_wtroot, C_DIM, row0, col0, smem_u32(smem), acc);
        expsum_epilogue(acc, g_part_root, NT_ROOT, row0, ct, smem);
    }
}

// ---------------- launch B: tail0 + tail1 4-row supertiles ------------------
__global__ void __launch_bounds__(256)
gemm_tails()
{
    extern __shared__ __align__(1024) char smem[];
    const uint32_t sBase = smem_u32(smem);
    const int tid = threadIdx.x;
    const int lane = tid & 31, wid = tid >> 5;
    const int warp_m = wid & 1, warp_n = wid >> 1;
    const int lane7 = lane & 7;
    const int b3 = (lane >> 3) & 1, b4 = (lane >> 4) & 1;
    const uint32_t aRowOff = (uint32_t)((warp_m * 64 + lane7 + 8 * b3) << 7);
    const uint32_t bRowOff = (uint32_t)((warp_n * 32 + lane7 + 8 * b3) << 7);
    uint32_t chunk[4];
#pragma unroll
    for (int ks = 0; ks < 4; ks++)
        chunk[ks] = (uint32_t)((((ks << 1) + b4) ^ lane7) << 4);

    const long long i = blockIdx.x;
    const int lo = (int)((i * NB_T1S) / NB_TAILS);
    const int hi = (int)(((i + 1) * NB_T1S) / NB_TAILS);
    float acc[4][4][4];

    if (hi > lo) {
        // ---- tail1 supertile: one B tile shared by FOUR row-tiles ----
        const int ct = lo % NT1, srt = lo / NT1;
        const int col0 = ct << 7;
        const int row0 = srt << 9;
        const int r0 = tid >> 3;
        const __nv_bfloat16* gB = g_wt1 + (size_t)(col0 + r0) * H1 + ((tid & 7) << 3);
        const __nv_bfloat16* gA = g_hcomb + 256 + (size_t)(row0 + r0) * HCOMB + ((tid & 7) << 3);
        const size_t strA = (size_t)HCOMB << 5, strB = (size_t)H1 << 5;
        const uint32_t soff = ((uint32_t)r0 << 7) + (uint32_t)(((tid & 7) ^ (r0 & 7)) << 4);

        {   // group0: B + A0
            uint32_t s = sBase + soff;
            const __nv_bfloat16 *pB = gB, *pA = gA;
#pragma unroll
            for (int q = 0; q < 4; q++) {
                cp_async16(s, pB);
                cp_async16(s + TILE_BYTES, pA);
                s += 4096; pB += strB; pA += strA;
            }
        }
        CP_COMMIT();
#pragma unroll
        for (int sub = 1; sub < 4; sub++) {
            uint32_t s = sBase + (uint32_t)(1 + sub) * TILE_BYTES + soff;
            const __nv_bfloat16* pA = gA + (size_t)(128 * sub) * HCOMB;
#pragma unroll
            for (int q = 0; q < 4; q++) {
                cp_async16(s, pA);
                s += 4096; pA += strA;
            }
            CP_COMMIT();
        }

        char* redmem = smem + 5 * TILE_BYTES;

#define DO_SUB(S, WAITN)                                                     \
        CP_WAIT_N(WAITN);                                                    \
        __syncthreads();                                                     \
        zero_acc(acc);                                                       \
        compute_tile(sBase + (uint32_t)(1 + (S)) * TILE_BYTES, sBase, acc,   \
                     chunk, aRowOff, bRowOff);                               \
        expsum_epilogue(acc, g_part1, NT1, row0 + 128 * (S), ct, redmem);    \
        __syncthreads();

        DO_SUB(0, 3)
        DO_SUB(1, 2)
        DO_SUB(2, 1)
        DO_SUB(3, 0)
#undef DO_SUB
    } else {
        // ---- tail0 tile ----
        const int tile = (int)i - lo;
        const int ct = tile % NT0, rt = tile / NT0;
        const int row0 = rt << 7, col0 = ct << 7;
        gemm_mainloop(g_hcomb, HCOMB, g_wt0, H0, row0, col0, sBase, acc);
        expsum_epilogue(acc, g_part0, NT0, row0, ct, smem);
    }
}

// ---------------- per-row: picked logits + LSE + CE (R14 version) ----------
__global__ __launch_bounds__(128)
void row_ce(const int* __restrict__ targets)
{
    int n   = blockIdx.x;
    int tid = threadIdx.x;
    int t   = targets[n];
    int rt  = (t < 2000) ? t : ((t < 10000) ? 2000 : 2001);
    int t0  = min(max(t - 2000, 0), D0 - 1);
    int t1  = min(max(t - 10000, 0), D1 - 1);

    float sr = 0.f, s0 = 0.f, s1 = 0.f;
    const __nv_bfloat16* xr = g_xbf + (size_t)n * C_DIM;
    const __nv_bfloat16* wr = g_wtroot + (size_t)rt * C_DIM;
#pragma unroll
    for (int i = 0; i < 4; i++) {
        int k = 2 * tid + i * 256;
        __nv_bfloat162 x2 = *reinterpret_cast<const __nv_bfloat162*>(xr + k);
        __nv_bfloat162 w2 = *reinterpret_cast<const __nv_bfloat162*>(wr + k);
        sr += __bfloat162float(x2.x) * __bfloat162float(w2.x)
            + __bfloat162float(x2.y) * __bfloat162float(w2.y);
    }
    const __nv_bfloat16* h = g_hcomb + (size_t)n * HCOMB;
    const __nv_bfloat16* w0 = g_wt0 + (size_t)t0 * H0;
#pragma unroll
    for (int i = 0; i < 2; i++) {
        int k = tid + i * 128;
        s0 += __bfloat162float(h[k]) * __bfloat162float(w0[k]);
    }
    if (tid < H1)
        s1 = __bfloat162float(h[256 + tid]) * __bfloat162float(g_wt1[(size_t)t1 * H1 + tid]);

    float pr = 0.f, p0 = 0.f, p1 = 0.f;
    if (tid < NT_ROOT) pr = g_part_root[(size_t)n * NT_ROOT + tid];
    for (int k = tid; k < NT0; k += 128) p0 += g_part0[(size_t)n * NT0 + k];
    for (int k = tid; k < NT1; k += 128) p1 += g_part1[(size_t)n * NT1 + k];

    __shared__ float sh[6][128];
    sh[0][tid] = sr; sh[1][tid] = s0; sh[2][tid] = s1;
    sh[3][tid] = pr; sh[4][tid] = p0; sh[5][tid] = p1;
    __syncthreads();
    for (int off = 64; off > 0; off >>= 1) {
        if (tid < off) {
#pragma unroll
            for (int q = 0; q < 6; q++) sh[q][tid] += sh[q][tid + off];
        }
        __syncthreads();
    }
    if (tid == 0) {
        g_ce[n]              = logf(sh[3][0] - PAD_ROOT) - sh[0][0] * LN2;
        g_ce[N_ROWS + n]     = logf(sh[4][0] - PAD_T0)   - sh[1][0] * LN2;
        g_ce[2 * N_ROWS + n] = logf(sh[5][0] - PAD_T1)   - sh[2][0] * LN2;
    }
}

// ---------------- final scalar: shuffle-based, 1 sync ----------------
__global__ __launch_bounds__(512)
void final_kernel(const int* __restrict__ targets, float* __restrict__ out)
{
    const int tid = threadIdx.x;
    const int lane = tid & 31, wid = tid >> 5;   // 16 warps
    float v0 = 0.f, v1 = 0.f, v2 = 0.f, v3 = 0.f, v4 = 0.f;
#pragma unroll
    for (int i = 0; i < 8; i++) {
        int n = tid + i * 512;
        v0 += g_ce[n];
        int t = targets[n];
        if (t >= 2000 && t < 10000) { v1 += g_ce[N_ROWS + n];     v2 += 1.f; }
        if (t >= 10000)             { v3 += g_ce[2 * N_ROWS + n]; v4 += 1.f; }
    }
#pragma unroll
    for (int off = 16; off > 0; off >>= 1) {
        v0 += __shfl_xor_sync(0xffffffffu, v0, off);
        v1 += __shfl_xor_sync(0xffffffffu, v1, off);
        v2 += __shfl_xor_sync(0xffffffffu, v2, off);
        v3 += __shfl_xor_sync(0xffffffffu, v3, off);
        v4 += __shfl_xor_sync(0xffffffffu, v4, off);
    }
    __shared__ float sh[5][16];
    if (lane == 0) {
        sh[0][wid] = v0; sh[1][wid] = v1; sh[2][wid] = v2;
        sh[3][wid] = v3; sh[4][wid] = v4;
    }
    __syncthreads();
    if (tid < 32) {
        float w0 = (lane < 16) ? sh[0][lane] : 0.f;
        float w1 = (lane < 16) ? sh[1][lane] : 0.f;
        float w2 = (lane < 16) ? sh[2][lane] : 0.f;
        float w3 = (lane < 16) ? sh[3][lane] : 0.f;
        float w4 = (lane < 16) ? sh[4][lane] : 0.f;
#pragma unroll
        for (int off = 8; off > 0; off >>= 1) {
            w0 += __shfl_xor_sync(0xffffffffu, w0, off);
            w1 += __shfl_xor_sync(0xffffffffu, w1, off);
            w2 += __shfl_xor_sync(0xffffffffu, w2, off);
            w3 += __shfl_xor_sync(0xffffffffu, w3, off);
            w4 += __shfl_xor_sync(0xffffffffu, w4, off);
        }
        if (lane == 0) {
            float root_loss = w0 / (float)N_ROWS;
            float l0 = w1 / fmaxf(w2, 1.f);
            float l1 = w3 / fmaxf(w4, 1.f);
            out[0] = (root_loss + l0 + l1) / 3.f;
        }
    }
}

// ---------------- host launch ----------------
extern "C" void kernel_launch(void* const* d_in, const int* in_sizes, int n_in,
                              void* d_out, int out_size)
{
    const float* logits      = (const float*)d_in[0];
    const int*   targets     = (const int*)  d_in[1];
    const float* head_kernel = (const float*)d_in[2];
    const float* proj0       = (const float*)d_in[3];
    const float* scale0      = (const float*)d_in[4];
    const float* proj1       = (const float*)d_in[5];
    const float* scale1      = (const float*)d_in[6];
    float* out = (float*)d_out;

    __nv_bfloat16* xbf;
    cudaGetSymbolAddress((void**)&xbf, g_xbf);

    cudaFuncSetAttribute(gemm_root_proj, cudaFuncAttributeMaxDynamicSharedMemorySize, SMEM_DYN);
    cudaFuncSetAttribute(gemm_tails,     cudaFuncAttributeMaxDynamicSharedMemorySize, SMEM_DYN);

    // 1. prep: convert + transposes
    prep_all<<<NB_PREP, 256>>>(logits, head_kernel, proj0, proj1, scale0, scale1);

    // 2. launch A: hcomb projection + root expsum
    gemm_root_proj<<<NB_A, 256, SMEM_DYN>>>(xbf);

    // 3. launch B: tail0 + tail1 4-row supertiles
    gemm_tails<<<NB_TAILS, 256, SMEM_DYN>>>();

    // 4. per-row CE (R14 1-row version), final scalar (shuffle reduction)
    row_ce<<<N_ROWS, 128>>>(targets);
    final_kernel<<<1, 512>>>(targets, out);
}

// round 17
// speedup vs baseline: 1.0189x; 1.0118x over previous
#include <cuda_runtime.h>
#include <cuda_bf16.h>
#include <cuda_fp16.h>
#include <math.h>
#include <stdint.h>

// ---------------- problem dims ----------------
#define N_ROWS 4096
#define C_DIM  1024
#define D_ROOT 2002
#define H0     256
#define H1     64
#define D0     8000
#define D1     40257

#define NT_ROOT 16
#define NT0     63
#define NT1     315
#define NG1     63            // tail1 col-groups of 5 tiles (315 = 63*5)
#define HCOMB   384

#define PAD_ROOT 46.f
#define PAD_T0   64.f
#define PAD_T1   63.f

#define LOG2E 1.4426950408889634f
#define LN2   0.6931471805599453f

#define TILE_BYTES  16384
#define STAGE3      32768
#define SMEM_DYN    (3 * STAGE3)

// launch A: proj (96) + root expsum (512)
#define NB_PROJ  96
#define NB_ROOT  (NT_ROOT * 32)              // 512
#define NB_A     (NB_PROJ + NB_ROOT)         // 608
// launch B: 1:1 interleave — even bids tail1 col-supertiles, odd bids tail0
#define NB_T0    (NT0 * 32)                  // 2016
#define NB_T1G   (NG1 * 32)                  // 2016 col-supertiles
#define NB_TAILS (NB_T0 + NB_T1G)            // 4032

// prep
#define NB_CONV  4096
#define NB_PREP  (NB_CONV + 6904)

// ---------------- scratch ----------------
__device__ __align__(16) __nv_bfloat16 g_xbf[N_ROWS * C_DIM];
__device__ __align__(16) __nv_bfloat16 g_hcomb[N_ROWS * HCOMB];
__device__ __align__(16) __nv_bfloat16 g_pt[HCOMB * C_DIM];
__device__ __align__(16) __nv_bfloat16 g_wtroot[NT_ROOT * 128 * C_DIM];   // * log2e
__device__ __align__(16) __nv_bfloat16 g_wt0[NT0 * 128 * H0];             // * log2e
__device__ __align__(16) __nv_bfloat16 g_wt1[(size_t)NT1 * 128 * H1];     // * log2e
__device__ float g_part_root[N_ROWS * NT_ROOT];
__device__ float g_part0[N_ROWS * NT0];
__device__ float g_part1[N_ROWS * NG1];     // 5 col-tiles pre-summed per entry
__device__ float g_ce[3 * N_ROWS];

// ---------------- helpers ----------------
static __device__ __forceinline__ uint32_t smem_u32(const void* p) {
    uint32_t r;
    asm("{ .reg .u64 t; cvta.to.shared.u64 t, %1; cvt.u32.u64 %0, t; }" : "=r"(r) : "l"(p));
    return r;
}
static __device__ __forceinline__ void cp_async16(uint32_t dst, const void* src) {
    asm volatile("cp.async.cg.shared.global [%0], [%1], 16;" :: "r"(dst), "l"(src));
}
// two exps in one MUFU op: 2^a + 2^b accumulated into p (f16x2 path)
static __device__ __forceinline__ void ex2_pair_acc(float a, float b, float& p) {
    __half2 h = __floats2half2_rn(a, b);
    uint32_t hr = *reinterpret_cast<uint32_t*>(&h);
    uint32_t er;
    asm("ex2.approx.f16x2 %0, %1;" : "=r"(er) : "r"(hr));
    __half2 e = *reinterpret_cast<__half2*>(&er);
    float2 f = __half22float2(e);
    p += f.x + f.y;
}
#define CP_COMMIT()   asm volatile("cp.async.commit_group;")
#define CP_WAIT1()    asm volatile("cp.async.wait_group 1;")
#define CP_WAIT_N(n)  asm volatile("cp.async.wait_group %0;" :: "n"(n))

#define LDSM4(r0, r1, r2, r3, addr) \
    asm volatile("ldmatrix.sync.aligned.m8n8.x4.shared.b16 {%0,%1,%2,%3}, [%4];" \
        : "=r"(r0), "=r"(r1), "=r"(r2), "=r"(r3) : "r"(addr))

#define MMA16816(d, a, b0, b1) \
    asm volatile("mma.sync.aligned.m16n8k16.row.col.f32.bf16.bf16.f32 " \
        "{%0,%1,%2,%3}, {%4,%5,%6,%7}, {%8,%9}, {%0,%1,%2,%3};" \
        : "+f"((d)[0]), "+f"((d)[1]), "+f"((d)[2]), "+f"((d)[3]) \
        : "r"((a)[0]), "r"((a)[1]), "r"((a)[2]), "r"((a)[3]), "r"(b0), "r"(b1))

static __device__ __forceinline__ void zero_acc(float acc[4][4][4]) {
#pragma unroll
    for (int i = 0; i < 4; i++)
#pragma unroll
        for (int j = 0; j < 4; j++)
#pragma unroll
            for (int q = 0; q < 4; q++) acc[i][j][q] = 0.f;
}

// one 128x128x64 tile of MMAs out of SMEM (A at sA, B at sB)
static __device__ __forceinline__ void compute_tile(
    uint32_t sA, uint32_t sB, float acc[4][4][4],
    const uint32_t chunk[4], uint32_t aRowOff, uint32_t bRowOff)
{
#pragma unroll
    for (int ks = 0; ks < 4; ks++) {
        uint32_t a[4][4], b[2][4];
#pragma unroll
        for (int mt = 0; mt < 4; mt++)
            LDSM4(a[mt][0], a[mt][1], a[mt][2], a[mt][3],
                  sA + aRowOff + (uint32_t)(mt << 11) + chunk[ks]);
#pragma unroll
        for (int np = 0; np < 2; np++)
            LDSM4(b[np][0], b[np][1], b[np][2], b[np][3],
                  sB + bRowOff + (uint32_t)(np << 11) + chunk[ks]);
#pragma unroll
        for (int mt = 0; mt < 4; mt++) {
#pragma unroll
            for (int np = 0; np < 2; np++) {
                MMA16816(acc[mt][2 * np],     a[mt], b[np][0], b[np][2]);
                MMA16816(acc[mt][2 * np + 1], a[mt], b[np][1], b[np][3]);
            }
        }
    }
}

// ---------------- 3-stage mainloop: 128x128 tile, BK=64 ----------------
static __device__ __forceinline__ void gemm_mainloop(
    const __nv_bfloat16* __restrict__ A, int lda,
    const __nv_bfloat16* __restrict__ B, int K,
    int row0, int col0, uint32_t sBase, float acc[4][4][4])
{
    const int tid = threadIdx.x;
    const int lane = tid & 31, wid = tid >> 5;
    const int warp_m = wid & 1, warp_n = wid >> 1;

    zero_acc(acc);

    const int r0 = tid >> 3;
    const __nv_bfloat16* gA = A + (size_t)(row0 + r0) * lda + ((tid & 7) << 3);
    const __nv_bfloat16* gB = B + (size_t)(col0 + r0) * K + ((tid & 7) << 3);
    const size_t strA = (size_t)lda << 5, strB = (size_t)K << 5;
    const uint32_t soff = ((uint32_t)r0 << 7) + (uint32_t)(((tid & 7) ^ (r0 & 7)) << 4);

    auto load_stage = [&](int stage, int kt) {
        uint32_t sA = sBase + (uint32_t)stage * STAGE3 + soff;
        const __nv_bfloat16* pA = gA + (kt << 6);
        const __nv_bfloat16* pB = gB + (kt << 6);
#pragma unroll
        for (int i = 0; i < 4; i++) {
            cp_async16(sA, pA);
            cp_async16(sA + TILE_BYTES, pB);
            sA += 4096; pA += strA; pB += strB;
        }
    };

    const int lane7 = lane & 7;
    const int b3 = (lane >> 3) & 1, b4 = (lane >> 4) & 1;
    const uint32_t aRowOff = (uint32_t)((warp_m * 64 + lane7 + 8 * b3) << 7);
    const uint32_t bRowOff = (uint32_t)((warp_n * 32 + lane7 + 8 * b3) << 7);
    uint32_t chunk[4];
#pragma unroll
    for (int ks = 0; ks < 4; ks++)
        chunk[ks] = (uint32_t)((((ks << 1) + b4) ^ lane7) << 4);

    const int nk = K >> 6;
    load_stage(0, 0);
    CP_COMMIT();
    if (nk > 1) load_stage(1, 1);
    CP_COMMIT();

    int stage = 0;
    for (int kt = 0; kt < nk; kt++) {
        CP_WAIT1();
        __syncthreads();
        const uint32_t sA = sBase + (uint32_t)stage * STAGE3;
        compute_tile(sA, sA + TILE_BYTES, acc, chunk, aRowOff, bRowOff);
        if (kt + 2 < nk) {
            int ps = stage + 2; if (ps >= 3) ps -= 3;
            load_stage(ps, kt + 2);
        }
        CP_COMMIT();
        if (++stage == 3) stage = 0;
    }
    __syncthreads();
}

// ---------------- shared exp-sum epilogue (f16x2 ex2) ----------------
static __device__ __forceinline__ void expsum_epilogue(
    float acc[4][4][4], float* part, int ntiles, int row0, int ct, char* redmem)
{
    const int tid = threadIdx.x;
    const int lane = tid & 31, wid = tid >> 5;
    const int warp_m = wid & 1, warp_n = wid >> 1;
    float* red = reinterpret_cast<float*>(redmem);
#pragma unroll
    for (int mt = 0; mt < 4; mt++) {
#pragma unroll
        for (int h = 0; h < 2; h++) {
            float p = 0.f;
#pragma unroll
            for (int nt = 0; nt < 4; nt++)
                ex2_pair_acc(acc[mt][nt][2 * h], acc[mt][nt][2 * h + 1], p);
            p += __shfl_xor_sync(0xffffffffu, p, 1);
            p += __shfl_xor_sync(0xffffffffu, p, 2);
            if ((lane & 3) == 0) {
                int r = warp_m * 64 + mt * 16 + (lane >> 2) + 8 * h;
                red[r * 4 + warp_n] = p;
            }
        }
    }
    __syncthreads();
    if (tid < 128) {
        float s = red[tid * 4] + red[tid * 4 + 1] + red[tid * 4 + 2] + red[tid * 4 + 3];
        part[(size_t)(row0 + tid) * ntiles + ct] = s;
    }
}

// exp-sum into smem staging only (no global store; caller accumulates)
static __device__ __forceinline__ void expsum_to_red(
    float acc[4][4][4], float* red)
{
    const int lane = threadIdx.x & 31, wid = threadIdx.x >> 5;
    const int warp_m = wid & 1, warp_n = wid >> 1;
#pragma unroll
    for (int mt = 0; mt < 4; mt++) {
#pragma unroll
        for (int h = 0; h < 2; h++) {
            float p = 0.f;
#pragma unroll
            for (int nt = 0; nt < 4; nt++)
                ex2_pair_acc(acc[mt][nt][2 * h], acc[mt][nt][2 * h + 1], p);
            p += __shfl_xor_sync(0xffffffffu, p, 1);
            p += __shfl_xor_sync(0xffffffffu, p, 2);
            if ((lane & 3) == 0) {
                int r = warp_m * 64 + mt * 16 + (lane >> 2) + 8 * h;
                red[r * 4 + warp_n] = p;
            }
        }
    }
}

// ---------------- prep: convert + all transposes in ONE launch ----------------
__global__ __launch_bounds__(256)
void prep_all(const float* __restrict__ logits,
              const float* __restrict__ head_kernel,
              const float* __restrict__ proj0, const float* __restrict__ proj1,
              const float* __restrict__ scale0, const float* __restrict__ scale1)
{
    int b = blockIdx.x;
    int tid = threadIdx.x;
    if (b < NB_CONV) {
        int i = b * 256 + tid;
        float4 v = reinterpret_cast<const float4*>(logits)[i];
        reinterpret_cast<__nv_bfloat162*>(g_xbf)[2 * i]     = __floats2bfloat162_rn(v.x, v.y);
        reinterpret_cast<__nv_bfloat162*>(g_xbf)[2 * i + 1] = __floats2bfloat162_rn(v.z, v.w);
        return;
    }
    b -= NB_CONV;
    const float* W; __nv_bfloat16* Wt; int K, D, nd; float sc = LOG2E;
    if (b < 2048)      { W = head_kernel; Wt = g_wtroot;            K = 1024; D = D_ROOT; nd = 64; }
    else if (b < 2304) { b -= 2048; W = proj0;  Wt = g_pt;              K = 1024; D = H0; nd = 8; sc = 1.f; }
    else if (b < 2368) { b -= 2304; W = proj1;  Wt = g_pt + 256 * 1024; K = 1024; D = H1; nd = 2; sc = 1.f; }
    else if (b < 4384) { b -= 2368; W = scale0; Wt = g_wt0;             K = 256;  D = D0; nd = 252; }
    else               { b -= 4384; W = scale1; Wt = g_wt1;             K = 64;   D = D1; nd = 1260; }
    int d0 = (b % nd) * 32, k0 = (b / nd) * 32;

    __shared__ float sh[32][33];
    int tx = tid & 31, ty = tid >> 5;
#pragma unroll
    for (int i = 0; i < 4; i++) {
        int k = k0 + ty + i * 8;
        int d = d0 + tx;
        sh[ty + i * 8][tx] = (d < D) ? W[(size_t)k * D + d] * sc : 0.f;
    }
    __syncthreads();
#pragma unroll
    for (int i = 0; i < 4; i++) {
        int drow = d0 + ty + i * 8;
        Wt[(size_t)drow * K + k0 + tx] = __float2bfloat16(sh[tx][ty + i * 8]);
    }
}

// ---------------- launch A: proj GEMM (96) + root expsum (512) -------------
__global__ void __launch_bounds__(256)
gemm_root_proj(const __nv_bfloat16* __restrict__ xbf)
{
    extern __shared__ __align__(1024) char smem[];
    int bid = blockIdx.x;
    float acc[4][4][4];

    if (bid < NB_PROJ) {
        const int ct = bid % 3, rt = bid / 3;
        const int row0 = rt << 7, col0 = ct << 7;
        gemm_mainloop(xbf, C_DIM, g_pt, C_DIM, row0, col0, smem_u32(smem), acc);
        const int lane = threadIdx.x & 31, wid = threadIdx.x >> 5;
        const int warp_m = wid & 1, warp_n = wid >> 1;
#pragma unroll
        for (int mt = 0; mt < 4; mt++) {
#pragma unroll
            for (int h = 0; h < 2; h++) {
                int row = row0 + warp_m * 64 + mt * 16 + (lane >> 2) + 8 * h;
#pragma unroll
                for (int nt = 0; nt < 4; nt++) {
                    int gc = col0 + warp_n * 32 + nt * 8 + 2 * (lane & 3);
                    __nv_bfloat162 v = __floats2bfloat162_rn(acc[mt][nt][2 * h],
                                                             acc[mt][nt][2 * h + 1]);
                    *reinterpret_cast<__nv_bfloat162*>(g_hcomb + (size_t)row * HCOMB + gc) = v;
                }
            }
        }
    } else {
        const int tile = bid - NB_PROJ;
        const int ct = tile % NT_ROOT, rt = tile / NT_ROOT;
        const int row0 = rt << 7, col0 = ct << 7;
        gemm_mainloop(xbf, C_DIM, g_wtroot, C_DIM, row0, col0, smem_u32(smem), acc);
        expsum_epilogue(acc, g_part_root, NT_ROOT, row0, ct, smem);
    }
}

// ---------------- launch B: 1:1 interleave of tail1 col-supertiles & tail0 --
__global__ void __launch_bounds__(256)
gemm_tails()
{
    extern __shared__ __align__(1024) char smem[];
    const uint32_t sBase = smem_u32(smem);
    const int tid = threadIdx.x;
    const int lane = tid & 31, wid = tid >> 5;
    const int warp_m = wid & 1, warp_n = wid >> 1;
    const int lane7 = lane & 7;
    const int b3 = (lane >> 3) & 1, b4 = (lane >> 4) & 1;
    const uint32_t aRowOff = (uint32_t)((warp_m * 64 + lane7 + 8 * b3) << 7);
    const uint32_t bRowOff = (uint32_t)((warp_n * 32 + lane7 + 8 * b3) << 7);
    uint32_t chunk[4];
#pragma unroll
    for (int ks = 0; ks < 4; ks++)
        chunk[ks] = (uint32_t)((((ks << 1) + b4) ^ lane7) << 4);

    const int bid = blockIdx.x;
    float acc[4][4][4];

    if ((bid & 1) == 0) {
        // ---- tail1 col-supertile: A tile resident, 5 B col-tiles streamed,
        //      row-sums accumulated in registers -> ONE part1 write ----
        const int idx = bid >> 1;              // 0..2015
        const int cg = idx % NG1, rt = idx / NG1;
        const int row0 = rt << 7;
        const int r0 = tid >> 3;
        const uint32_t soff = ((uint32_t)r0 << 7) + (uint32_t)(((tid & 7) ^ (r0 & 7)) << 4);
        const __nv_bfloat16* gA = g_hcomb + 256 + (size_t)(row0 + r0) * HCOMB + ((tid & 7) << 3);
        const size_t strA = (size_t)HCOMB << 5;
        const __nv_bfloat16* gB = g_wt1 + ((size_t)(cg * 5) * 128 + r0) * H1 + ((tid & 7) << 3);
        const size_t strB = (size_t)H1 << 5;   // 32 rows of B tile
        const size_t tileB = (size_t)128 * H1; // elems between col tiles (16KB)

        {   // group 0: A (resident) + B0
            uint32_t s = sBase + soff;
            const __nv_bfloat16 *pA = gA, *pB = gB;
#pragma unroll
            for (int q = 0; q < 4; q++) {
                cp_async16(s, pA);
                cp_async16(s + TILE_BYTES, pB);
                s += 4096; pA += strA; pB += strB;
            }
        }
        CP_COMMIT();
        {   // group 1: B1
            uint32_t s = sBase + 2 * TILE_BYTES + soff;
            const __nv_bfloat16* pB = gB + tileB;
#pragma unroll
            for (int q = 0; q < 4; q++) {
                cp_async16(s, pB);
                s += 4096; pB += strB;
            }
        }
        CP_COMMIT();

        float* red = reinterpret_cast<float*>(smem + 3 * TILE_BYTES);
        float racc = 0.f;

#pragma unroll
        for (int t = 0; t < 5; t++) {
            CP_WAIT_N(1);
            __syncthreads();                       // B(t) ready; prev red consumed
            zero_acc(acc);
            compute_tile(sBase, sBase + (uint32_t)(1 + (t & 1)) * TILE_BYTES,
                         acc, chunk, aRowOff, bRowOff);
            expsum_to_red(acc, red);
            __syncthreads();                       // red visible; B(t) LDSM done
            if (t + 2 < 5) {                       // prefetch B(t+2) into buf(t&1)
                uint32_t s = sBase + (uint32_t)(1 + (t & 1)) * TILE_BYTES + soff;
                const __nv_bfloat16* pB = gB + (size_t)(t + 2) * tileB;
#pragma unroll
                for (int q = 0; q < 4; q++) {
                    cp_async16(s, pB);
                    s += 4096; pB += strB;
                }
            }
            CP_COMMIT();                           // keep group count uniform
            if (tid < 128)
                racc += red[tid * 4] + red[tid * 4 + 1]
                      + red[tid * 4 + 2] + red[tid * 4 + 3];
        }
        if (tid < 128)
            g_part1[(size_t)(row0 + tid) * NG1 + cg] = racc;
    } else {
        // ---- tail0 tile ----
        const int tile = bid >> 1;                 // 0..2015
        const int ct = tile % NT0, rt = tile / NT0;
        const int row0 = rt << 7, col0 = ct << 7;
        gemm_mainloop(g_hcomb, HCOMB, g_wt0, H0, row0, col0, sBase, acc);
        expsum_epilogue(acc, g_part0, NT0, row0, ct, smem);
    }
}

// ---------------- per-row: picked logits + LSE + CE ----------------
__global__ __launch_bounds__(128)
void row_ce(const int* __restrict__ targets)
{
    int n   = blockIdx.x;
    int tid = threadIdx.x;
    int t   = targets[n];
    int rt  = (t < 2000) ? t : ((t < 10000) ? 2000 : 2001);
    int t0  = min(max(t - 2000, 0), D0 - 1);
    int t1  = min(max(t - 10000, 0), D1 - 1);

    float sr = 0.f, s0 = 0.f, s1 = 0.f;
    const __nv_bfloat16* xr = g_xbf + (size_t)n * C_DIM;
    const __nv_bfloat16* wr = g_wtroot + (size_t)rt * C_DIM;
#pragma unroll
    for (int i = 0; i < 4; i++) {
        int k = 2 * tid + i * 256;
        __nv_bfloat162 x2 = *reinterpret_cast<const __nv_bfloat162*>(xr + k);
        __nv_bfloat162 w2 = *reinterpret_cast<const __nv_bfloat162*>(wr + k);
        sr += __bfloat162float(x2.x) * __bfloat162float(w2.x)
            + __bfloat162float(x2.y) * __bfloat162float(w2.y);
    }
    const __nv_bfloat16* h = g_hcomb + (size_t)n * HCOMB;
    const __nv_bfloat16* w0 = g_wt0 + (size_t)t0 * H0;
#pragma unroll
    for (int i = 0; i < 2; i++) {
        int k = tid + i * 128;
        s0 += __bfloat162float(h[k]) * __bfloat162float(w0[k]);
    }
    if (tid < H1)
        s1 = __bfloat162float(h[256 + tid]) * __bfloat162float(g_wt1[(size_t)t1 * H1 + tid]);

    float pr = 0.f, p0 = 0.f, p1 = 0.f;
    if (tid < NT_ROOT) pr = g_part_root[(size_t)n * NT_ROOT + tid];
    for (int k = tid; k < NT0; k += 128) p0 += g_part0[(size_t)n * NT0 + k];
    if (tid < NG1) p1 = g_part1[(size_t)n * NG1 + tid];

    __shared__ float sh[6][128];
    sh[0][tid] = sr; sh[1][tid] = s0; sh[2][tid] = s1;
    sh[3][tid] = pr; sh[4][tid] = p0; sh[5][tid] = p1;
    __syncthreads();
    for (int off = 64; off > 0; off >>= 1) {
        if (tid < off) {
#pragma unroll
            for (int q = 0; q < 6; q++) sh[q][tid] += sh[q][tid + off];
        }
        __syncthreads();
    }
    if (tid == 0) {
        g_ce[n]              = logf(sh[3][0] - PAD_ROOT) - sh[0][0] * LN2;
        g_ce[N_ROWS + n]     = logf(sh[4][0] - PAD_T0)   - sh[1][0] * LN2;
        g_ce[2 * N_ROWS + n] = logf(sh[5][0] - PAD_T1)   - sh[2][0] * LN2;
    }
}

// ---------------- final scalar ----------------
__global__ __launch_bounds__(1024)
void final_kernel(const int* __restrict__ targets, float* __restrict__ out)
{
    int tid = threadIdx.x;
    float sr = 0.f, s0 = 0.f, c0 = 0.f, s1 = 0.f, c1 = 0.f;
    for (int n = tid; n < N_ROWS; n += 1024) {
        sr += g_ce[n];
        int t = targets[n];
        if (t >= 2000 && t < 10000) { s0 += g_ce[N_ROWS + n];     c0 += 1.f; }
        if (t >= 10000)             { s1 += g_ce[2 * N_ROWS + n]; c1 += 1.f; }
    }
    __shared__ float sh[5][1024];
    sh[0][tid] = sr; sh[1][tid] = s0; sh[2][tid] = c0; sh[3][tid] = s1; sh[4][tid] = c1;
    __syncthreads();
    for (int off = 512; off > 0; off >>= 1) {
        if (tid < off) {
#pragma unroll
            for (int q = 0; q < 5; q++) sh[q][tid] += sh[q][tid + off];
        }
        __syncthreads();
    }
    if (tid == 0) {
        float root_loss = sh[0][0] / (float)N_ROWS;
        float l0 = sh[1][0] / fmaxf(sh[2][0], 1.f);
        float l1 = sh[3][0] / fmaxf(sh[4][0], 1.f);
        out[0] = (root_loss + l0 + l1) / 3.f;
    }
}

// ---------------- host launch ----------------
extern "C" void kernel_launch(void* const* d_in, const int* in_sizes, int n_in,
                              void* d_out, int out_size)
{
    const float* logits      = (const float*)d_in[0];
    const int*   targets     = (const int*)  d_in[1];
    const float* head_kernel = (const float*)d_in[2];
    const float* proj0       = (const float*)d_in[3];
    const float* scale0      = (const float*)d_in[4];
    const float* proj1       = (const float*)d_in[5];
    const float* scale1      = (const float*)d_in[6];
    float* out = (float*)d_out;

    __nv_bfloat16* xbf;
    cudaGetSymbolAddress((void**)&xbf, g_xbf);

    cudaFuncSetAttribute(gemm_root_proj, cudaFuncAttributeMaxDynamicSharedMemorySize, SMEM_DYN);
    cudaFuncSetAttribute(gemm_tails,     cudaFuncAttributeMaxDynamicSharedMemorySize, SMEM_DYN);

    // 1. prep: convert + transposes
    prep_all<<<NB_PREP, 256>>>(logits, head_kernel, proj0, proj1, scale0, scale1);

    // 2. launch A: hcomb projection + root expsum
    gemm_root_proj<<<NB_A, 256, SMEM_DYN>>>(xbf);

    // 3. launch B: tail1 col-supertiles + tail0, 1:1 interleave
    gemm_tails<<<NB_TAILS, 256, SMEM_DYN>>>();

    // 4. per-row CE, final scalar
    row_ce<<<N_ROWS, 128>>>(targets);
    final_kernel<<<1, 1024>>>(targets, out);
}